// round 15
// baseline (speedup 1.0000x reference)
#include <cuda_runtime.h>

#define HID 16
#define MAXN 4096
#define TAB 2048
#define CHUNKS 8

__device__ float4 g_pifrac[MAXN];
__device__ float  g_C[9];        // cell / pi
__device__ float  g_tscale;      // dist -> table coordinate scale
__device__ float  g_tabs[2 * TAB];  // scalar eta tables; [cls*TAB + i] = f(s_i)

__device__ __forceinline__ float tanh_ap(float x) {
    float y;
    asm("tanh.approx.f32 %0, %1;" : "=f"(y) : "f"(x));
    return y;
}

// Setup: cell constants per-block; table build with 16 lanes per entry
// (lane owns one layer-2 column, half-warp butterfly reduce); pifrac + out copy.
__global__ void __launch_bounds__(256) setup_kernel(
    const float* __restrict__ x, const float* __restrict__ cell,
    const float* __restrict__ Wp1, const float* __restrict__ bp1,
    const float* __restrict__ Wp2, const float* __restrict__ bp2,
    const float* __restrict__ Wp3, const float* __restrict__ bp3,
    const float* __restrict__ Wa1, const float* __restrict__ ba1,
    const float* __restrict__ Wa2, const float* __restrict__ ba2,
    const float* __restrict__ Wa3, const float* __restrict__ ba3,
    float* __restrict__ out, int n)
{
    __shared__ float sh[10];   // sinv[9], sstep
    const float PI = 3.14159265358979323846f;

    if (threadIdx.x == 0) {
        float c[9];
#pragma unroll
        for (int i = 0; i < 9; i++) c[i] = cell[i];
        float det = c[0]*(c[4]*c[8]-c[5]*c[7])
                  - c[1]*(c[3]*c[8]-c[5]*c[6])
                  + c[2]*(c[3]*c[7]-c[4]*c[6]);
        float id = 1.0f / det;
        sh[0]=(c[4]*c[8]-c[5]*c[7])*id; sh[1]=(c[2]*c[7]-c[1]*c[8])*id; sh[2]=(c[1]*c[5]-c[2]*c[4])*id;
        sh[3]=(c[5]*c[6]-c[3]*c[8])*id; sh[4]=(c[0]*c[8]-c[2]*c[6])*id; sh[5]=(c[2]*c[3]-c[0]*c[5])*id;
        sh[6]=(c[3]*c[7]-c[4]*c[6])*id; sh[7]=(c[1]*c[6]-c[0]*c[7])*id; sh[8]=(c[0]*c[4]-c[1]*c[3])*id;
        float volpp = fabsf(det) / (float)n;
        float invrs = cbrtf(4.0f * PI / (3.0f * volpp));   // 1/rs
        float C0 = c[0]/PI, C1 = c[1]/PI, C2 = c[2]/PI;
        float C3 = c[3]/PI, C4 = c[4]/PI, C5 = c[5]/PI;
        float C6 = c[6]/PI, C7 = c[7]/PI, C8 = c[8]/PI;
        float r0 = sqrtf(C0*C0 + C1*C1 + C2*C2);
        float r1 = sqrtf(C3*C3 + C4*C4 + C5*C5);
        float r2 = sqrtf(C6*C6 + C7*C7 + C8*C8);
        float smax = (r0 + r1 + r2) * invrs * 1.0001f;
        sh[9] = smax / (float)(TAB - 1);                   // sstep
        if (blockIdx.x == 0) {
            g_C[0]=C0; g_C[1]=C1; g_C[2]=C2;
            g_C[3]=C3; g_C[4]=C4; g_C[5]=C5;
            g_C[6]=C6; g_C[7]=C7; g_C[8]=C8;
            g_tscale = invrs * (float)(TAB - 1) / smax;
        }
    }
    __syncthreads();

    int t = blockIdx.x * 256 + threadIdx.x;

    // ---- table build: 16 threads per entry ----
    int e = t >> 4;                 // entry index in [0, 2*TAB)
    if (e < 2 * TAB) {
        int cls = e >> 11;          // TAB = 2048
        int i   = e & (TAB - 1);
        int c   = t & 15;           // this lane's layer-2 column
        float s = (float)i * sh[9];

        const float* W1 = cls ? Wa1 : Wp1;
        const float* b1 = cls ? ba1 : bp1;
        const float* W2 = cls ? Wa2 : Wp2;
        const float* b2 = cls ? ba2 : bp2;
        const float* W3 = cls ? Wa3 : Wp3;
        const float* b3 = cls ? ba3 : bp3;

        float g = b2[c];
#pragma unroll
        for (int k = 0; k < HID; k++) {
            float h = tanh_ap(fmaf(s, W1[k], b1[k]));
            g = fmaf(h, W2[k*HID + c], g);
        }
        float f = tanh_ap(g) * W3[c];
        // half-warp butterfly reduce (offsets 1,2,4,8 stay within 16-lane group)
#pragma unroll
        for (int o = 1; o < 16; o <<= 1)
            f += __shfl_xor_sync(0xffffffffu, f, o);
        if (c == 0) g_tabs[cls * TAB + i] = f + b3[0];
    }

    // ---- pifrac (padded to 32 multiple) + out copy ----
    int npad = (n + 31) & ~31;
    int gsz  = gridDim.x * 256;
    for (int i = t; i < npad; i += gsz) {
        if (i < n) {
            float x0 = x[3*i+0], x1 = x[3*i+1], x2 = x[3*i+2];
            float f0 = x0*sh[0] + x1*sh[3] + x2*sh[6];
            float f1 = x0*sh[1] + x1*sh[4] + x2*sh[7];
            float f2 = x0*sh[2] + x1*sh[5] + x2*sh[8];
            g_pifrac[i] = make_float4(PI*f0, PI*f1, PI*f2, 0.f);
            out[3*i+0] = x0; out[3*i+1] = x1; out[3*i+2] = x2;
        } else {
            g_pifrac[i] = make_float4(0.f, 0.f, 0.f, 0.f);
        }
    }
}

// Pair kernel: one warp per (j, chunk) work item, exact cover (no grid-stride).
// Table staged in shared memory. Fast path: segment length == 6*32 exactly
// (compile-time trip count). Generic dynamic loop otherwise.
__global__ void __launch_bounds__(256) pair_kernel(
    const int* __restrict__ n_up_ptr, float* __restrict__ out, int n)
{
    __shared__ float s_tab[2 * TAB];
    {
        const float4* src = (const float4*)g_tabs;
        float4*       dst = (float4*)s_tab;
#pragma unroll
        for (int t = threadIdx.x; t < (2 * TAB) / 4; t += 256)
            dst[t] = src[t];
    }
    __syncthreads();

    int lane   = threadIdx.x & 31;
    int w      = (blockIdx.x * blockDim.x + threadIdx.x) >> 5;
    int totalWork = n * CHUNKS;
    if (w >= totalWork) return;
    int csz = (n + CHUNKS - 1) / CHUNKS;

    int   n_up   = *n_up_ptr;
    float tscale = g_tscale;
    float C00=g_C[0], C01=g_C[1], C02=g_C[2];
    float C10=g_C[3], C11=g_C[4], C12=g_C[5];
    float C20=g_C[6], C21=g_C[7], C22=g_C[8];

    int j    = w >> 3;                  // CHUNKS = 8
    int ibeg = (w & (CHUNKS - 1)) * csz;
    int iend = ibeg + csz; if (iend > n) iend = n;
    if (ibeg >= iend) return;

    bool   j_up = (j < n_up);
    float4 pfj  = g_pifrac[j];
    float acc0 = 0.f, acc1 = 0.f, acc2 = 0.f;

    bool straddle = (ibeg < n_up) && (n_up < iend);
    int  nseg     = straddle ? 2 : 1;

    for (int seg = 0; seg < nseg; seg++) {
        int rb = (seg == 0) ? ibeg : n_up;
        int re = (straddle && seg == 0) ? n_up : iend;
        const float* tb = s_tab + ((((rb < n_up) == j_up) ? 0 : 1) * TAB);

        if (re - rb == 6 * 32) {
            // ---- fast path: compile-time trip count of 6 ----
            int base = rb + lane;
#pragma unroll 3
            for (int k = 0; k < 6; k++) {
                int i = base + (k << 5);
                float4 pfi = g_pifrac[i];
                float s0 = __sinf(pfj.x - pfi.x);
                float s1 = __sinf(pfj.y - pfi.y);
                float s2 = __sinf(pfj.z - pfi.z);
                float v0 = s0*C00 + s1*C10 + s2*C20;
                float v1 = s0*C01 + s1*C11 + s2*C21;
                float v2 = s0*C02 + s1*C12 + s2*C22;
                float q  = v0*v0 + v1*v1 + v2*v2;
                float dist;
                asm("sqrt.approx.f32 %0, %1;" : "=f"(dist) : "f"(q));

                float t   = dist * tscale;
                int   idx = (int)t;
                idx = idx < (TAB - 2) ? idx : (TAB - 2);
                float fr  = t - (float)idx;
                float f0  = tb[idx];
                float f1  = tb[idx + 1];
                float eta = fmaf(fr, f1 - f0, f0);
                if (i == j) eta = 0.f;

                acc0 = fmaf(eta, v0, acc0);
                acc1 = fmaf(eta, v1, acc1);
                acc2 = fmaf(eta, v2, acc2);
            }
        } else {
            // ---- generic path ----
            for (int i = rb + lane; i < re; i += 32) {
                float4 pfi = g_pifrac[i];
                float s0 = __sinf(pfj.x - pfi.x);
                float s1 = __sinf(pfj.y - pfi.y);
                float s2 = __sinf(pfj.z - pfi.z);
                float v0 = s0*C00 + s1*C10 + s2*C20;
                float v1 = s0*C01 + s1*C11 + s2*C21;
                float v2 = s0*C02 + s1*C12 + s2*C22;
                float q  = v0*v0 + v1*v1 + v2*v2;
                float dist;
                asm("sqrt.approx.f32 %0, %1;" : "=f"(dist) : "f"(q));

                float t   = dist * tscale;
                int   idx = (int)t;
                idx = idx < (TAB - 2) ? idx : (TAB - 2);
                float fr  = t - (float)idx;
                float f0  = tb[idx];
                float f1  = tb[idx + 1];
                float eta = fmaf(fr, f1 - f0, f0);
                if (i == j) eta = 0.f;

                acc0 = fmaf(eta, v0, acc0);
                acc1 = fmaf(eta, v1, acc1);
                acc2 = fmaf(eta, v2, acc2);
            }
        }
    }

#pragma unroll
    for (int o = 16; o > 0; o >>= 1) {
        acc0 += __shfl_xor_sync(0xffffffffu, acc0, o);
        acc1 += __shfl_xor_sync(0xffffffffu, acc1, o);
        acc2 += __shfl_xor_sync(0xffffffffu, acc2, o);
    }
    if (lane == 0) {
        atomicAdd(&out[3*j+0], acc0);
        atomicAdd(&out[3*j+1], acc1);
        atomicAdd(&out[3*j+2], acc2);
    }
}

extern "C" void kernel_launch(void* const* d_in, const int* in_sizes, int n_in,
                              void* d_out, int out_size) {
    const float* x    = (const float*)d_in[0];
    const float* cell = (const float*)d_in[1];
    const float* Wp1  = (const float*)d_in[2];
    const float* bp1  = (const float*)d_in[3];
    const float* Wp2  = (const float*)d_in[4];
    const float* bp2  = (const float*)d_in[5];
    const float* Wp3  = (const float*)d_in[6];
    const float* bp3  = (const float*)d_in[7];
    const float* Wa1  = (const float*)d_in[8];
    const float* ba1  = (const float*)d_in[9];
    const float* Wa2  = (const float*)d_in[10];
    const float* ba2  = (const float*)d_in[11];
    const float* Wa3  = (const float*)d_in[12];
    const float* ba3  = (const float*)d_in[13];
    const int*   n_up = (const int*)d_in[14];
    float* out = (float*)d_out;

    int n = in_sizes[0] / 3;
    int tabThreads = 2 * TAB * 16;                       // 16 lanes per entry
    setup_kernel<<<(tabThreads + 255) / 256, 256>>>(x, cell,
                                                    Wp1, bp1, Wp2, bp2, Wp3, bp3,
                                                    Wa1, ba1, Wa2, ba2, Wa3, ba3,
                                                    out, n);
    // one item per warp: n*CHUNKS warps exactly
    int blocks = (n * CHUNKS * 32 + 255) / 256;
    pair_kernel<<<blocks, 256>>>(n_up, out, n);
}

// round 16
// speedup vs baseline: 1.1630x; 1.1630x over previous
#include <cuda_runtime.h>

#define HID 16
#define MAXN 4096
#define TAB 1024
#define CHUNKS 6

__device__ float4 g_pifrac[MAXN];
__device__ float  g_C[9];        // cell / pi
__device__ float  g_tscale;      // dist -> table coordinate scale
__device__ float  g_tabs[2 * TAB];  // scalar eta tables; [cls*TAB + i] = f(s_i)

__device__ __forceinline__ float tanh_ap(float x) {
    float y;
    asm("tanh.approx.f32 %0, %1;" : "=f"(y) : "f"(x));
    return y;
}

// Setup: cell constants per-block; table build with 16 lanes per entry
// (lane owns one layer-2 column, half-warp butterfly reduce); pifrac + out copy.
__global__ void __launch_bounds__(256) setup_kernel(
    const float* __restrict__ x, const float* __restrict__ cell,
    const float* __restrict__ Wp1, const float* __restrict__ bp1,
    const float* __restrict__ Wp2, const float* __restrict__ bp2,
    const float* __restrict__ Wp3, const float* __restrict__ bp3,
    const float* __restrict__ Wa1, const float* __restrict__ ba1,
    const float* __restrict__ Wa2, const float* __restrict__ ba2,
    const float* __restrict__ Wa3, const float* __restrict__ ba3,
    float* __restrict__ out, int n)
{
    __shared__ float sh[10];   // sinv[9], sstep
    const float PI = 3.14159265358979323846f;

    if (threadIdx.x == 0) {
        float c[9];
#pragma unroll
        for (int i = 0; i < 9; i++) c[i] = cell[i];
        float det = c[0]*(c[4]*c[8]-c[5]*c[7])
                  - c[1]*(c[3]*c[8]-c[5]*c[6])
                  + c[2]*(c[3]*c[7]-c[4]*c[6]);
        float id = 1.0f / det;
        sh[0]=(c[4]*c[8]-c[5]*c[7])*id; sh[1]=(c[2]*c[7]-c[1]*c[8])*id; sh[2]=(c[1]*c[5]-c[2]*c[4])*id;
        sh[3]=(c[5]*c[6]-c[3]*c[8])*id; sh[4]=(c[0]*c[8]-c[2]*c[6])*id; sh[5]=(c[2]*c[3]-c[0]*c[5])*id;
        sh[6]=(c[3]*c[7]-c[4]*c[6])*id; sh[7]=(c[1]*c[6]-c[0]*c[7])*id; sh[8]=(c[0]*c[4]-c[1]*c[3])*id;
        float volpp = fabsf(det) / (float)n;
        float invrs = cbrtf(4.0f * PI / (3.0f * volpp));   // 1/rs
        float C0 = c[0]/PI, C1 = c[1]/PI, C2 = c[2]/PI;
        float C3 = c[3]/PI, C4 = c[4]/PI, C5 = c[5]/PI;
        float C6 = c[6]/PI, C7 = c[7]/PI, C8 = c[8]/PI;
        float r0 = sqrtf(C0*C0 + C1*C1 + C2*C2);
        float r1 = sqrtf(C3*C3 + C4*C4 + C5*C5);
        float r2 = sqrtf(C6*C6 + C7*C7 + C8*C8);
        float smax = (r0 + r1 + r2) * invrs * 1.0001f;
        sh[9] = smax / (float)(TAB - 1);                   // sstep
        if (blockIdx.x == 0) {
            g_C[0]=C0; g_C[1]=C1; g_C[2]=C2;
            g_C[3]=C3; g_C[4]=C4; g_C[5]=C5;
            g_C[6]=C6; g_C[7]=C7; g_C[8]=C8;
            g_tscale = invrs * (float)(TAB - 1) / smax;
        }
    }
    __syncthreads();

    int t = blockIdx.x * 256 + threadIdx.x;

    // ---- table build: 16 threads per entry ----
    int e = t >> 4;                 // entry index in [0, 2*TAB)
    if (e < 2 * TAB) {
        int cls = e >> 10;          // TAB = 1024
        int i   = e & (TAB - 1);
        int c   = t & 15;           // this lane's layer-2 column
        float s = (float)i * sh[9];

        const float* W1 = cls ? Wa1 : Wp1;
        const float* b1 = cls ? ba1 : bp1;
        const float* W2 = cls ? Wa2 : Wp2;
        const float* b2 = cls ? ba2 : bp2;
        const float* W3 = cls ? Wa3 : Wp3;
        const float* b3 = cls ? ba3 : bp3;

        float g = b2[c];
#pragma unroll
        for (int k = 0; k < HID; k++) {
            float h = tanh_ap(fmaf(s, W1[k], b1[k]));
            g = fmaf(h, W2[k*HID + c], g);
        }
        float f = tanh_ap(g) * W3[c];
        // half-warp butterfly reduce (offsets 1,2,4,8 stay within 16-lane group)
#pragma unroll
        for (int o = 1; o < 16; o <<= 1)
            f += __shfl_xor_sync(0xffffffffu, f, o);
        if (c == 0) g_tabs[cls * TAB + i] = f + b3[0];
    }

    // ---- pifrac (padded to 32 multiple) + out copy ----
    int npad = (n + 31) & ~31;
    int gsz  = gridDim.x * 256;
    for (int i = t; i < npad; i += gsz) {
        if (i < n) {
            float x0 = x[3*i+0], x1 = x[3*i+1], x2 = x[3*i+2];
            float f0 = x0*sh[0] + x1*sh[3] + x2*sh[6];
            float f1 = x0*sh[1] + x1*sh[4] + x2*sh[7];
            float f2 = x0*sh[2] + x1*sh[5] + x2*sh[8];
            g_pifrac[i] = make_float4(PI*f0, PI*f1, PI*f2, 0.f);
            out[3*i+0] = x0; out[3*i+1] = x1; out[3*i+2] = x2;
        } else {
            g_pifrac[i] = make_float4(0.f, 0.f, 0.f, 0.f);
        }
    }
}

// Pair kernel: one warp per (j, chunk) work item, exact cover in ONE wave
// (CHUNKS=6 -> 9216 warps <= chip residency at 32 regs). Table (8 KB) staged
// in shared memory. Fast path: segment length == 8*32 (compile-time trips).
__global__ void __launch_bounds__(256) pair_kernel(
    const int* __restrict__ n_up_ptr, float* __restrict__ out, int n)
{
    __shared__ float s_tab[2 * TAB];
    {
        const float4* src = (const float4*)g_tabs;
        float4*       dst = (float4*)s_tab;
#pragma unroll
        for (int t = threadIdx.x; t < (2 * TAB) / 4; t += 256)
            dst[t] = src[t];
    }
    __syncthreads();

    int lane = threadIdx.x & 31;
    int w    = (blockIdx.x * blockDim.x + threadIdx.x) >> 5;
    int totalWork = n * CHUNKS;
    if (w >= totalWork) return;
    int csz = (n + CHUNKS - 1) / CHUNKS;

    int   n_up   = *n_up_ptr;
    float tscale = g_tscale;
    float C00=g_C[0], C01=g_C[1], C02=g_C[2];
    float C10=g_C[3], C11=g_C[4], C12=g_C[5];
    float C20=g_C[6], C21=g_C[7], C22=g_C[8];

    int j     = w / CHUNKS;
    int chunk = w - j * CHUNKS;
    int ibeg  = chunk * csz;
    int iend  = ibeg + csz; if (iend > n) iend = n;
    if (ibeg >= iend) return;

    bool   j_up = (j < n_up);
    float4 pfj  = g_pifrac[j];
    float acc0 = 0.f, acc1 = 0.f, acc2 = 0.f;

    bool straddle = (ibeg < n_up) && (n_up < iend);
    int  nseg     = straddle ? 2 : 1;

    for (int seg = 0; seg < nseg; seg++) {
        int rb = (seg == 0) ? ibeg : n_up;
        int re = (straddle && seg == 0) ? n_up : iend;
        const float* tb = s_tab + ((((rb < n_up) == j_up) ? 0 : 1) * TAB);

        if (re - rb == 8 * 32) {
            // ---- fast path: compile-time trip count of 8 ----
            int base = rb + lane;
#pragma unroll 4
            for (int k = 0; k < 8; k++) {
                int i = base + (k << 5);
                float4 pfi = g_pifrac[i];
                float s0 = __sinf(pfj.x - pfi.x);
                float s1 = __sinf(pfj.y - pfi.y);
                float s2 = __sinf(pfj.z - pfi.z);
                float v0 = s0*C00 + s1*C10 + s2*C20;
                float v1 = s0*C01 + s1*C11 + s2*C21;
                float v2 = s0*C02 + s1*C12 + s2*C22;
                float q  = v0*v0 + v1*v1 + v2*v2;
                float dist;
                asm("sqrt.approx.f32 %0, %1;" : "=f"(dist) : "f"(q));

                float t   = dist * tscale;
                int   idx = (int)t;
                idx = idx < (TAB - 2) ? idx : (TAB - 2);
                float fr  = t - (float)idx;
                float f0  = tb[idx];
                float f1  = tb[idx + 1];
                float eta = fmaf(fr, f1 - f0, f0);
                if (i == j) eta = 0.f;

                acc0 = fmaf(eta, v0, acc0);
                acc1 = fmaf(eta, v1, acc1);
                acc2 = fmaf(eta, v2, acc2);
            }
        } else {
            // ---- generic path ----
            for (int i = rb + lane; i < re; i += 32) {
                float4 pfi = g_pifrac[i];
                float s0 = __sinf(pfj.x - pfi.x);
                float s1 = __sinf(pfj.y - pfi.y);
                float s2 = __sinf(pfj.z - pfi.z);
                float v0 = s0*C00 + s1*C10 + s2*C20;
                float v1 = s0*C01 + s1*C11 + s2*C21;
                float v2 = s0*C02 + s1*C12 + s2*C22;
                float q  = v0*v0 + v1*v1 + v2*v2;
                float dist;
                asm("sqrt.approx.f32 %0, %1;" : "=f"(dist) : "f"(q));

                float t   = dist * tscale;
                int   idx = (int)t;
                idx = idx < (TAB - 2) ? idx : (TAB - 2);
                float fr  = t - (float)idx;
                float f0  = tb[idx];
                float f1  = tb[idx + 1];
                float eta = fmaf(fr, f1 - f0, f0);
                if (i == j) eta = 0.f;

                acc0 = fmaf(eta, v0, acc0);
                acc1 = fmaf(eta, v1, acc1);
                acc2 = fmaf(eta, v2, acc2);
            }
        }
    }

#pragma unroll
    for (int o = 16; o > 0; o >>= 1) {
        acc0 += __shfl_xor_sync(0xffffffffu, acc0, o);
        acc1 += __shfl_xor_sync(0xffffffffu, acc1, o);
        acc2 += __shfl_xor_sync(0xffffffffu, acc2, o);
    }
    if (lane == 0) {
        atomicAdd(&out[3*j+0], acc0);
        atomicAdd(&out[3*j+1], acc1);
        atomicAdd(&out[3*j+2], acc2);
    }
}

extern "C" void kernel_launch(void* const* d_in, const int* in_sizes, int n_in,
                              void* d_out, int out_size) {
    const float* x    = (const float*)d_in[0];
    const float* cell = (const float*)d_in[1];
    const float* Wp1  = (const float*)d_in[2];
    const float* bp1  = (const float*)d_in[3];
    const float* Wp2  = (const float*)d_in[4];
    const float* bp2  = (const float*)d_in[5];
    const float* Wp3  = (const float*)d_in[6];
    const float* bp3  = (const float*)d_in[7];
    const float* Wa1  = (const float*)d_in[8];
    const float* ba1  = (const float*)d_in[9];
    const float* Wa2  = (const float*)d_in[10];
    const float* ba2  = (const float*)d_in[11];
    const float* Wa3  = (const float*)d_in[12];
    const float* ba3  = (const float*)d_in[13];
    const int*   n_up = (const int*)d_in[14];
    float* out = (float*)d_out;

    int n = in_sizes[0] / 3;
    int tabThreads = 2 * TAB * 16;                       // 16 lanes per entry
    setup_kernel<<<(tabThreads + 255) / 256, 256>>>(x, cell,
                                                    Wp1, bp1, Wp2, bp2, Wp3, bp3,
                                                    Wa1, ba1, Wa2, ba2, Wa3, ba3,
                                                    out, n);
    // one item per warp: n*CHUNKS warps in a single resident wave
    int blocks = (n * CHUNKS * 32 + 255) / 256;
    pair_kernel<<<blocks, 256>>>(n_up, out, n);
}